// round 1
// baseline (speedup 1.0000x reference)
#include <cuda_runtime.h>
#include <cstdint>
#include <cstddef>

// Problem dims
#define S_IMGC 2304
#define S_TXTC 512
#define S_TOTC 2816
#define DMC    3072
#define NHC    24
#define HDC    128

// ---------------- scratch (static __device__, allocation-guard safe) ----------------
__device__ float g_sQ[S_TOTC * DMC];
__device__ float g_sK[S_TOTC * DMC];
__device__ float g_sV[S_TOTC * DMC];
__device__ float g_Qh[(size_t)NHC * S_TOTC * HDC];
__device__ float g_Kh[(size_t)NHC * S_TOTC * HDC];
__device__ float g_Vt[(size_t)NHC * HDC * S_TOTC];   // [h][d][s]
__device__ float g_P [(size_t)NHC * S_TOTC * S_TOTC]; // scores/probs, 761 MB
__device__ float g_O [(size_t)S_TOTC * DMC];          // attn out, token-major

// ---------------- tf32 mma GEMM: C = alpha * A @ B^T (+ bias), batched ----------------
// A: [M,K] row-major (lda), B: [N,K] row-major (ldb), C: [M,N] (ldc)
// All of M%128==0, N%128==0, K%32==0 guaranteed by call sites.

#define BM 128
#define BN 128
#define BKT 32
#define SROW 36                      // BK + 4 pad (bank-conflict-free frag loads)
#define STAGE_A (BM * SROW)
#define STAGE_B (BN * SROW)
#define GEMM_SMEM_BYTES ((2 * STAGE_A + 2 * STAGE_B) * 4)

struct GemmP {
    const float* A; const float* B; float* C;
    long long lda, ldb, ldc;
    long long sA, sB, sC;
    const float* bias;
    float alpha;
    int ktiles;
};

__device__ __forceinline__ void cpasync16(float* smem, const float* gmem) {
    uint32_t s = (uint32_t)__cvta_generic_to_shared(smem);
    asm volatile("cp.async.cg.shared.global [%0], [%1], 16;\n" :: "r"(s), "l"(gmem));
}

__device__ __forceinline__ uint32_t f2tf32(float x) {
    uint32_t r;
    asm("cvt.rna.tf32.f32 %0, %1;\n" : "=r"(r) : "f"(x));
    return r;
}

__device__ __forceinline__ void mma_tf32(float* c, const uint32_t* a, const uint32_t* b) {
    asm volatile(
        "mma.sync.aligned.m16n8k8.row.col.f32.tf32.tf32.f32 "
        "{%0,%1,%2,%3},{%4,%5,%6,%7},{%8,%9},{%0,%1,%2,%3};\n"
        : "+f"(c[0]), "+f"(c[1]), "+f"(c[2]), "+f"(c[3])
        : "r"(a[0]), "r"(a[1]), "r"(a[2]), "r"(a[3]), "r"(b[0]), "r"(b[1]));
}

__device__ __forceinline__ void load_tile(float* Ss, const float* G, long long ld,
                                          int rowl, int chl, long long koff) {
#pragma unroll
    for (int i = 0; i < 8; i++) {
        int r = rowl + i * 16;
        cpasync16(Ss + r * SROW + chl, G + (long long)r * ld + koff + chl);
    }
}

__global__ __launch_bounds__(128, 2) void gemm_tf32(GemmP p) {
    extern __shared__ float smem[];
    float* sA = smem;
    float* sB = smem + 2 * STAGE_A;

    int tid = threadIdx.x;
    const float* A = p.A + (long long)blockIdx.z * p.sA + (long long)blockIdx.y * BM * p.lda;
    const float* B = p.B + (long long)blockIdx.z * p.sB + (long long)blockIdx.x * BN * p.ldb;

    int rowl = tid >> 3;        // 0..15
    int chl  = (tid & 7) * 4;   // float offset of 16B chunk

    int wid = tid >> 5, lane = tid & 31;
    int wm = (wid & 1) * 64, wn = (wid >> 1) * 64;  // warp tile 64x64, warps 2x2
    int g = lane >> 2, tg = lane & 3;

    float c[4][8][4];
#pragma unroll
    for (int mt = 0; mt < 4; mt++)
#pragma unroll
        for (int nt = 0; nt < 8; nt++)
#pragma unroll
            for (int r = 0; r < 4; r++) c[mt][nt][r] = 0.f;

    load_tile(sA, A, p.lda, rowl, chl, 0);
    load_tile(sB, B, p.ldb, rowl, chl, 0);
    asm volatile("cp.async.commit_group;\n" ::: "memory");

    for (int kt = 0; kt < p.ktiles; kt++) {
        if (kt + 1 < p.ktiles) {
            int b = (kt + 1) & 1;
            load_tile(sA + b * STAGE_A, A, p.lda, rowl, chl, (long long)(kt + 1) * BKT);
            load_tile(sB + b * STAGE_B, B, p.ldb, rowl, chl, (long long)(kt + 1) * BKT);
            asm volatile("cp.async.commit_group;\n" ::: "memory");
            asm volatile("cp.async.wait_group 1;\n" ::: "memory");
        } else {
            asm volatile("cp.async.wait_group 0;\n" ::: "memory");
        }
        __syncthreads();

        const float* bA = sA + (kt & 1) * STAGE_A;
        const float* bB = sB + (kt & 1) * STAGE_B;

#pragma unroll
        for (int ks = 0; ks < 4; ks++) {
            int k0 = ks * 8 + tg;
            uint32_t af[4][4];
#pragma unroll
            for (int mt = 0; mt < 4; mt++) {
                const float* base = bA + (wm + mt * 16 + g) * SROW + k0;
                af[mt][0] = f2tf32(base[0]);
                af[mt][1] = f2tf32(base[8 * SROW]);
                af[mt][2] = f2tf32(base[4]);
                af[mt][3] = f2tf32(base[8 * SROW + 4]);
            }
            uint32_t bf[8][2];
#pragma unroll
            for (int nt = 0; nt < 8; nt++) {
                const float* base = bB + (wn + nt * 8 + g) * SROW + k0;
                bf[nt][0] = f2tf32(base[0]);
                bf[nt][1] = f2tf32(base[4]);
            }
#pragma unroll
            for (int mt = 0; mt < 4; mt++)
#pragma unroll
                for (int nt = 0; nt < 8; nt++)
                    mma_tf32(c[mt][nt], af[mt], bf[nt]);
        }
        __syncthreads();
    }

    // Epilogue
    float* C = p.C + (long long)blockIdx.z * p.sC;
    long long r0base = (long long)blockIdx.y * BM;
    long long c0base = (long long)blockIdx.x * BN;
#pragma unroll
    for (int mt = 0; mt < 4; mt++) {
#pragma unroll
        for (int nt = 0; nt < 8; nt++) {
            long long col = c0base + wn + nt * 8 + tg * 2;
            float b0 = 0.f, b1 = 0.f;
            if (p.bias) { b0 = p.bias[col]; b1 = p.bias[col + 1]; }
            long long r = r0base + wm + mt * 16 + g;
            float2 v0 = make_float2(p.alpha * c[mt][nt][0] + b0, p.alpha * c[mt][nt][1] + b1);
            *(float2*)(C + r * p.ldc + col) = v0;
            float2 v1 = make_float2(p.alpha * c[mt][nt][2] + b0, p.alpha * c[mt][nt][3] + b1);
            *(float2*)(C + (r + 8) * p.ldc + col) = v1;
        }
    }
}

// ---------------- RMSNorm + RoPE + layout transform ----------------
// blockIdx.y: 0 -> Q, 1 -> K, 2 -> V. One warp per (token, head).
__global__ __launch_bounds__(256) void qkv_prep(
    const float* __restrict__ sQ, const float* __restrict__ sK, const float* __restrict__ sV,
    const float* __restrict__ nq, const float* __restrict__ nk,
    const float* __restrict__ naq, const float* __restrict__ nak,
    const float* __restrict__ img_cos, const float* __restrict__ img_sin,
    const float* __restrict__ txt_cos, const float* __restrict__ txt_sin,
    float* __restrict__ Qh, float* __restrict__ Kh, float* __restrict__ Vt)
{
    int unit = blockIdx.x * 8 + (threadIdx.x >> 5);
    int lane = threadIdx.x & 31;
    int which = blockIdx.y;
    if (unit >= S_TOTC * NHC) return;
    int tok = unit / NHC;
    int h = unit % NHC;

    const float* src = (which == 0) ? sQ : (which == 1) ? sK : sV;
    float4 x = *(const float4*)&src[(long long)tok * DMC + h * HDC + lane * 4];

    if (which < 2) {
        float ss = x.x * x.x + x.y * x.y + x.z * x.z + x.w * x.w;
#pragma unroll
        for (int o = 16; o > 0; o >>= 1) ss += __shfl_xor_sync(0xffffffffu, ss, o);
        float r = rsqrtf(ss * (1.0f / 128.0f) + 1e-6f);
        const float* nw = (which == 0) ? (tok < S_TXTC ? naq : nq)
                                       : (tok < S_TXTC ? nak : nk);
        float4 w = *(const float4*)&nw[lane * 4];
        x.x *= r * w.x; x.y *= r * w.y; x.z *= r * w.z; x.w *= r * w.w;

        const float* ct; const float* st; int tr;
        if (tok < S_TXTC) { ct = txt_cos; st = txt_sin; tr = tok; }
        else              { ct = img_cos; st = img_sin; tr = tok - S_TXTC; }
        int p0 = lane * 2;
        float c0 = ct[tr * 64 + p0],     s0 = st[tr * 64 + p0];
        float c1 = ct[tr * 64 + p0 + 1], s1 = st[tr * 64 + p0 + 1];
        float o0 = x.x * c0 - x.y * s0;
        float o1 = x.x * s0 + x.y * c0;
        float o2 = x.z * c1 - x.w * s1;
        float o3 = x.z * s1 + x.w * c1;
        x = make_float4(o0, o1, o2, o3);

        float* dst = (which == 0) ? Qh : Kh;
        *(float4*)&dst[((long long)h * S_TOTC + tok) * HDC + lane * 4] = x;
    } else {
        // V transposed: Vt[h][d][s]
        float* dst = Vt + (long long)h * HDC * S_TOTC;
        int d = lane * 4;
        dst[(long long)(d + 0) * S_TOTC + tok] = x.x;
        dst[(long long)(d + 1) * S_TOTC + tok] = x.y;
        dst[(long long)(d + 2) * S_TOTC + tok] = x.z;
        dst[(long long)(d + 3) * S_TOTC + tok] = x.w;
    }
}

// ---------------- row softmax over 2816 columns (one block per row) ----------------
__global__ __launch_bounds__(256) void softmax_kernel(float* __restrict__ P) {
    __shared__ float sred[8];
    __shared__ float sbc;
    size_t base = (size_t)blockIdx.x * S_TOTC;
    int t = threadIdx.x;
    float v[11];
    float mx = -3.0e38f;
#pragma unroll
    for (int i = 0; i < 11; i++) { v[i] = P[base + t + i * 256]; mx = fmaxf(mx, v[i]); }
#pragma unroll
    for (int o = 16; o > 0; o >>= 1) mx = fmaxf(mx, __shfl_xor_sync(0xffffffffu, mx, o));
    if ((t & 31) == 0) sred[t >> 5] = mx;
    __syncthreads();
    if (t == 0) {
        float m = sred[0];
#pragma unroll
        for (int i = 1; i < 8; i++) m = fmaxf(m, sred[i]);
        sbc = m;
    }
    __syncthreads();
    mx = sbc;
    float s = 0.f;
#pragma unroll
    for (int i = 0; i < 11; i++) { v[i] = __expf(v[i] - mx); s += v[i]; }
#pragma unroll
    for (int o = 16; o > 0; o >>= 1) s += __shfl_xor_sync(0xffffffffu, s, o);
    __syncthreads();
    if ((t & 31) == 0) sred[t >> 5] = s;
    __syncthreads();
    if (t == 0) {
        float tot = 0.f;
#pragma unroll
        for (int i = 0; i < 8; i++) tot += sred[i];
        sbc = 1.0f / tot;
    }
    __syncthreads();
    float inv = sbc;
#pragma unroll
    for (int i = 0; i < 11; i++) P[base + t + i * 256] = v[i] * inv;
}

// ---------------- host orchestration ----------------
static void launch_gemm(const float* A, long long lda, long long sA,
                        const float* B, long long ldb, long long sB,
                        float* C, long long ldc, long long sC,
                        int M, int N, int K, int batch,
                        float alpha, const float* bias)
{
    GemmP p;
    p.A = A; p.B = B; p.C = C;
    p.lda = lda; p.ldb = ldb; p.ldc = ldc;
    p.sA = sA; p.sB = sB; p.sC = sC;
    p.bias = bias; p.alpha = alpha; p.ktiles = K / BKT;
    dim3 grid((unsigned)(N / BN), (unsigned)(M / BM), (unsigned)batch);
    gemm_tf32<<<grid, 128, GEMM_SMEM_BYTES>>>(p);
}

extern "C" void kernel_launch(void* const* d_in, const int* in_sizes, int n_in,
                              void* d_out, int out_size) {
    (void)in_sizes; (void)n_in; (void)out_size;

    const float* hidden  = (const float*)d_in[0];
    const float* enc     = (const float*)d_in[1];
    const float* wq  = (const float*)d_in[2];  const float* bq  = (const float*)d_in[3];
    const float* wk  = (const float*)d_in[4];  const float* bk  = (const float*)d_in[5];
    const float* wv  = (const float*)d_in[6];  const float* bv  = (const float*)d_in[7];
    const float* waq = (const float*)d_in[8];  const float* baq = (const float*)d_in[9];
    const float* wak = (const float*)d_in[10]; const float* bak = (const float*)d_in[11];
    const float* wav = (const float*)d_in[12]; const float* bav = (const float*)d_in[13];
    const float* nq  = (const float*)d_in[14]; const float* nk  = (const float*)d_in[15];
    const float* naq = (const float*)d_in[16]; const float* nak = (const float*)d_in[17];
    const float* w_out = (const float*)d_in[18]; const float* b_out = (const float*)d_in[19];
    const float* w_add = (const float*)d_in[20]; const float* b_add = (const float*)d_in[21];
    const float* img_cos = (const float*)d_in[22]; const float* img_sin = (const float*)d_in[23];
    const float* txt_cos = (const float*)d_in[24]; const float* txt_sin = (const float*)d_in[25];
    float* out = (float*)d_out;

    float *sQp, *sKp, *sVp, *Qhp, *Khp, *Vtp, *Pp, *Op;
    cudaGetSymbolAddress((void**)&sQp, g_sQ);
    cudaGetSymbolAddress((void**)&sKp, g_sK);
    cudaGetSymbolAddress((void**)&sVp, g_sV);
    cudaGetSymbolAddress((void**)&Qhp, g_Qh);
    cudaGetSymbolAddress((void**)&Khp, g_Kh);
    cudaGetSymbolAddress((void**)&Vtp, g_Vt);
    cudaGetSymbolAddress((void**)&Pp,  g_P);
    cudaGetSymbolAddress((void**)&Op,  g_O);

    cudaFuncSetAttribute(gemm_tf32, cudaFuncAttributeMaxDynamicSharedMemorySize, GEMM_SMEM_BYTES);

    // 1) QKV projections (txt rows [0,512), img rows [512,2816) in token-major scratch)
    launch_gemm(hidden, DMC, 0, wq,  DMC, 0, sQp + (long long)S_TXTC * DMC, DMC, 0, S_IMGC, DMC, DMC, 1, 1.f, bq);
    launch_gemm(enc,    DMC, 0, waq, DMC, 0, sQp,                           DMC, 0, S_TXTC, DMC, DMC, 1, 1.f, baq);
    launch_gemm(hidden, DMC, 0, wk,  DMC, 0, sKp + (long long)S_TXTC * DMC, DMC, 0, S_IMGC, DMC, DMC, 1, 1.f, bk);
    launch_gemm(enc,    DMC, 0, wak, DMC, 0, sKp,                           DMC, 0, S_TXTC, DMC, DMC, 1, 1.f, bak);
    launch_gemm(hidden, DMC, 0, wv,  DMC, 0, sVp + (long long)S_TXTC * DMC, DMC, 0, S_IMGC, DMC, DMC, 1, 1.f, bv);
    launch_gemm(enc,    DMC, 0, wav, DMC, 0, sVp,                           DMC, 0, S_TXTC, DMC, DMC, 1, 1.f, bav);

    // 2) RMSNorm + RoPE + head-major / transposed layouts
    qkv_prep<<<dim3((S_TOTC * NHC) / 8, 3), 256>>>(
        sQp, sKp, sVp, nq, nk, naq, nak,
        img_cos, img_sin, txt_cos, txt_sin, Qhp, Khp, Vtp);

    // 3) scores = scale * Q @ K^T, per head
    launch_gemm(Qhp, HDC, (long long)S_TOTC * HDC,
                Khp, HDC, (long long)S_TOTC * HDC,
                Pp, S_TOTC, (long long)S_TOTC * S_TOTC,
                S_TOTC, S_TOTC, HDC, NHC, 0.08838834764831845f, nullptr);

    // 4) softmax over rows
    softmax_kernel<<<NHC * S_TOTC, 256>>>(Pp);

    // 5) O = P @ V, written token-major (ldc=3072, head stride 128)
    launch_gemm(Pp, S_TOTC, (long long)S_TOTC * S_TOTC,
                Vtp, S_TOTC, (long long)HDC * S_TOTC,
                Op, DMC, HDC,
                S_TOTC, HDC, S_TOTC, NHC, 1.f, nullptr);

    // 6) output projections (img first in d_out, then txt)
    launch_gemm(Op + (long long)S_TXTC * DMC, DMC, 0, w_out, DMC, 0,
                out, DMC, 0, S_IMGC, DMC, DMC, 1, 1.f, b_out);
    launch_gemm(Op, DMC, 0, w_add, DMC, 0,
                out + (long long)S_IMGC * DMC, DMC, 0, S_TXTC, DMC, DMC, 1, 1.f, b_add);
}

// round 10
// speedup vs baseline: 1.0907x; 1.0907x over previous
#include <cuda_runtime.h>
#include <cstdint>
#include <cstddef>

// Problem dims
#define S_IMGC 2304
#define S_TXTC 512
#define S_TOTC 2816
#define DMC    3072
#define NHC    24
#define HDC    128

// ---------------- scratch (static __device__, allocation-guard safe) ----------------
__device__ float g_sQ[S_TOTC * DMC];
__device__ float g_sK[S_TOTC * DMC];
__device__ float g_sV[S_TOTC * DMC];
__device__ float g_Qh[(size_t)NHC * S_TOTC * HDC];
__device__ float g_Kh[(size_t)NHC * S_TOTC * HDC];
__device__ float g_Vh[(size_t)NHC * S_TOTC * HDC];   // head-major [h][s][d] (no transpose)
__device__ float g_P [(size_t)NHC * S_TOTC * S_TOTC]; // scores/probs
__device__ float g_O [(size_t)S_TOTC * DMC];          // attn out, token-major

// ---------------- multi-job tf32 GEMM ----------------
// Computes, per job j = blockIdx.z:
//   C = alpha * A @ op(B) + bias
// BT=false: B is [N,K] row-major (C = A @ B^T)
// BT=true : B is [K,N] row-major (C = A @ B)

#define MAXJ 24
struct GemmP {
    const float* Aa[MAXJ];
    const float* Ba[MAXJ];
    float*       Ca[MAXJ];
    const float* biasa[MAXJ];
    int          my[MAXJ];
    long long lda, ldb, ldc;
    float alpha;
    int ktiles;
};

__device__ __forceinline__ void cpasync16(float* smem, const float* gmem) {
    uint32_t s = (uint32_t)__cvta_generic_to_shared(smem);
    asm volatile("cp.async.cg.shared.global [%0], [%1], 16;\n" :: "r"(s), "l"(gmem));
}

__device__ __forceinline__ uint32_t f2tf32(float x) {
    uint32_t r;
    asm("cvt.rna.tf32.f32 %0, %1;\n" : "=r"(r) : "f"(x));
    return r;
}

__device__ __forceinline__ void mma_tf32(float* c, const uint32_t* a, const uint32_t* b) {
    asm volatile(
        "mma.sync.aligned.m16n8k8.row.col.f32.tf32.tf32.f32 "
        "{%0,%1,%2,%3},{%4,%5,%6,%7},{%8,%9},{%0,%1,%2,%3};\n"
        : "+f"(c[0]), "+f"(c[1]), "+f"(c[2]), "+f"(c[3])
        : "r"(a[0]), "r"(a[1]), "r"(a[2]), "r"(a[3]), "r"(b[0]), "r"(b[1]));
}

// Load a [ROWS x 32] K-major tile into smem rows of stride 36 (pad -> conflict-free frags)
template<int ROWS>
__device__ __forceinline__ void load_km(float* Ss, const float* G, long long ld,
                                        int tid, long long koff) {
    int rowl = tid >> 3;            // 0..31
    int chl  = (tid & 7) * 4;       // 16B chunk within the 32-float row
#pragma unroll
    for (int r = rowl; r < ROWS; r += 32)
        cpasync16(Ss + r * 36 + chl, G + (long long)r * ld + koff + chl);
}

// Load a [32 x BN] tile of a [K,N] row-major matrix into smem [32][BN+8]
template<int BN>
__device__ __forceinline__ void load_nt(float* Ss, const float* G, long long ld,
                                        int tid, long long koff) {
    constexpr int CPR   = BN / 4;        // 16B chunks per row
    constexpr int RSTEP = 256 / CPR;     // rows covered per pass by 256 threads
    int rowl = tid / CPR;
    int chl  = (tid % CPR) * 4;
#pragma unroll
    for (int r = rowl; r < 32; r += RSTEP)
        cpasync16(Ss + r * (BN + 8) + chl, G + (koff + r) * ld + chl);
}

template<int BM, int BN, bool BT>
__global__ __launch_bounds__(256, 1) void gemm_tf32(GemmP p) {
    constexpr int SROW  = 36;
    constexpr int SROWB = BN + 8;                       // only used when BT
    constexpr int STA   = BM * SROW;
    constexpr int STB   = BT ? 32 * SROWB : BN * SROW;
    constexpr int NST   = 3;
    constexpr int WM    = BM / 64;                      // warps along M (8 warps total)

    extern __shared__ float smem[];
    float* sAb = smem;
    float* sBb = smem + NST * STA;

    int j = blockIdx.z;
    if ((int)blockIdx.y >= p.my[j]) return;

    int tid = threadIdx.x;
    const float* A = p.Aa[j] + (long long)blockIdx.y * BM * p.lda;
    const float* B = p.Ba[j] + (BT ? (long long)blockIdx.x * BN
                                   : (long long)blockIdx.x * BN * p.ldb);

    int wid = tid >> 5, lane = tid & 31;
    int wm = (wid % WM) * 64;
    int wn = (wid / WM) * 64;
    int g = lane >> 2, tg = lane & 3;

    float c[4][8][4];
#pragma unroll
    for (int mt = 0; mt < 4; mt++)
#pragma unroll
        for (int nt = 0; nt < 8; nt++)
#pragma unroll
            for (int r = 0; r < 4; r++) c[mt][nt][r] = 0.f;

    // prologue: stages 0,1
    int npro = p.ktiles < 2 ? p.ktiles : 2;
    for (int s = 0; s < npro; s++) {
        load_km<BM>(sAb + s * STA, A, p.lda, tid, (long long)s * 32);
        if constexpr (BT) load_nt<BN>(sBb + s * STB, B, p.ldb, tid, (long long)s * 32);
        else              load_km<BN>(sBb + s * STB, B, p.ldb, tid, (long long)s * 32);
        asm volatile("cp.async.commit_group;\n" ::: "memory");
    }

    for (int kt = 0; kt < p.ktiles; kt++) {
        if (kt < p.ktiles - 1) asm volatile("cp.async.wait_group 1;\n" ::: "memory");
        else                   asm volatile("cp.async.wait_group 0;\n" ::: "memory");
        __syncthreads();

        if (kt + 2 < p.ktiles) {
            int s = (kt + 2) % NST;
            load_km<BM>(sAb + s * STA, A, p.lda, tid, (long long)(kt + 2) * 32);
            if constexpr (BT) load_nt<BN>(sBb + s * STB, B, p.ldb, tid, (long long)(kt + 2) * 32);
            else              load_km<BN>(sBb + s * STB, B, p.ldb, tid, (long long)(kt + 2) * 32);
            asm volatile("cp.async.commit_group;\n" ::: "memory");
        }

        const float* bA = sAb + (kt % NST) * STA;
        const float* bB = sBb + (kt % NST) * STB;

#pragma unroll
        for (int ks = 0; ks < 4; ks++) {
            int k0 = ks * 8 + tg;
            uint32_t af[4][4];
#pragma unroll
            for (int mt = 0; mt < 4; mt++) {
                const float* base = bA + (wm + mt * 16 + g) * SROW + k0;
                af[mt][0] = f2tf32(base[0]);
                af[mt][1] = f2tf32(base[8 * SROW]);
                af[mt][2] = f2tf32(base[4]);
                af[mt][3] = f2tf32(base[8 * SROW + 4]);
            }
            uint32_t bf[8][2];
#pragma unroll
            for (int nt = 0; nt < 8; nt++) {
                if constexpr (BT) {
                    const float* base = bB + k0 * SROWB + wn + nt * 8 + g;
                    bf[nt][0] = f2tf32(base[0]);
                    bf[nt][1] = f2tf32(base[4 * SROWB]);
                } else {
                    const float* base = bB + (wn + nt * 8 + g) * SROW + k0;
                    bf[nt][0] = f2tf32(base[0]);
                    bf[nt][1] = f2tf32(base[4]);
                }
            }
#pragma unroll
            for (int mt = 0; mt < 4; mt++)
#pragma unroll
                for (int nt = 0; nt < 8; nt++)
                    mma_tf32(c[mt][nt], af[mt], bf[nt]);
        }
        __syncthreads();
    }

    // epilogue
    float* C = p.Ca[j];
    const float* bias = p.biasa[j];
    long long r0 = (long long)blockIdx.y * BM + wm;
    long long c0 = (long long)blockIdx.x * BN + wn;
#pragma unroll
    for (int mt = 0; mt < 4; mt++) {
#pragma unroll
        for (int nt = 0; nt < 8; nt++) {
            long long col = c0 + nt * 8 + tg * 2;
            float b0 = 0.f, b1 = 0.f;
            if (bias) { b0 = bias[col]; b1 = bias[col + 1]; }
            long long r = r0 + mt * 16 + g;
            float2 v0 = make_float2(p.alpha * c[mt][nt][0] + b0, p.alpha * c[mt][nt][1] + b1);
            *(float2*)(C + r * p.ldc + col) = v0;
            float2 v1 = make_float2(p.alpha * c[mt][nt][2] + b0, p.alpha * c[mt][nt][3] + b1);
            *(float2*)(C + (r + 8) * p.ldc + col) = v1;
        }
    }
}

// ---------------- RMSNorm + RoPE + layout transform ----------------
// blockIdx.y: 0 -> Q, 1 -> K, 2 -> V. One warp per (token, head).
__global__ __launch_bounds__(256) void qkv_prep(
    const float* __restrict__ sQ, const float* __restrict__ sK, const float* __restrict__ sV,
    const float* __restrict__ nq, const float* __restrict__ nk,
    const float* __restrict__ naq, const float* __restrict__ nak,
    const float* __restrict__ img_cos, const float* __restrict__ img_sin,
    const float* __restrict__ txt_cos, const float* __restrict__ txt_sin,
    float* __restrict__ Qh, float* __restrict__ Kh, float* __restrict__ Vh)
{
    int unit = blockIdx.x * 8 + (threadIdx.x >> 5);
    int lane = threadIdx.x & 31;
    int which = blockIdx.y;
    if (unit >= S_TOTC * NHC) return;
    int tok = unit / NHC;
    int h = unit % NHC;

    const float* src = (which == 0) ? sQ : (which == 1) ? sK : sV;
    float4 x = *(const float4*)&src[(long long)tok * DMC + h * HDC + lane * 4];

    if (which < 2) {
        float ss = x.x * x.x + x.y * x.y + x.z * x.z + x.w * x.w;
#pragma unroll
        for (int o = 16; o > 0; o >>= 1) ss += __shfl_xor_sync(0xffffffffu, ss, o);
        float r = rsqrtf(ss * (1.0f / 128.0f) + 1e-6f);
        const float* nw = (which == 0) ? (tok < S_TXTC ? naq : nq)
                                       : (tok < S_TXTC ? nak : nk);
        float4 w = *(const float4*)&nw[lane * 4];
        x.x *= r * w.x; x.y *= r * w.y; x.z *= r * w.z; x.w *= r * w.w;

        const float* ct; const float* st; int tr;
        if (tok < S_TXTC) { ct = txt_cos; st = txt_sin; tr = tok; }
        else              { ct = img_cos; st = img_sin; tr = tok - S_TXTC; }
        int p0 = lane * 2;
        float c0 = ct[tr * 64 + p0],     s0 = st[tr * 64 + p0];
        float c1 = ct[tr * 64 + p0 + 1], s1 = st[tr * 64 + p0 + 1];
        float o0 = x.x * c0 - x.y * s0;
        float o1 = x.x * s0 + x.y * c0;
        float o2 = x.z * c1 - x.w * s1;
        float o3 = x.z * s1 + x.w * c1;
        x = make_float4(o0, o1, o2, o3);

        float* dst = (which == 0) ? Qh : Kh;
        *(float4*)&dst[((long long)h * S_TOTC + tok) * HDC + lane * 4] = x;
    } else {
        // V head-major [h][s][d] — coalesced float4 store, no transpose
        *(float4*)&Vh[((long long)h * S_TOTC + tok) * HDC + lane * 4] = x;
    }
}

// ---------------- row softmax over 2816 columns (one block per row) ----------------
__global__ __launch_bounds__(256) void softmax_kernel(float* __restrict__ P) {
    __shared__ float sred[8];
    __shared__ float sbc;
    size_t base = (size_t)blockIdx.x * S_TOTC;
    int t = threadIdx.x;
    float v[11];
    float mx = -3.0e38f;
#pragma unroll
    for (int i = 0; i < 11; i++) { v[i] = P[base + t + i * 256]; mx = fmaxf(mx, v[i]); }
#pragma unroll
    for (int o = 16; o > 0; o >>= 1) mx = fmaxf(mx, __shfl_xor_sync(0xffffffffu, mx, o));
    if ((t & 31) == 0) sred[t >> 5] = mx;
    __syncthreads();
    if (t == 0) {
        float m = sred[0];
#pragma unroll
        for (int i = 1; i < 8; i++) m = fmaxf(m, sred[i]);
        sbc = m;
    }
    __syncthreads();
    mx = sbc;
    float s = 0.f;
#pragma unroll
    for (int i = 0; i < 11; i++) { v[i] = __expf(v[i] - mx); s += v[i]; }
#pragma unroll
    for (int o = 16; o > 0; o >>= 1) s += __shfl_xor_sync(0xffffffffu, s, o);
    __syncthreads();
    if ((t & 31) == 0) sred[t >> 5] = s;
    __syncthreads();
    if (t == 0) {
        float tot = 0.f;
#pragma unroll
        for (int i = 0; i < 8; i++) tot += sred[i];
        sbc = 1.0f / tot;
    }
    __syncthreads();
    float inv = sbc;
#pragma unroll
    for (int i = 0; i < 11; i++) P[base + t + i * 256] = v[i] * inv;
}

// ---------------- host orchestration ----------------
static constexpr int smem_bytes(int BM, int BN, bool BT) {
    int sta = BM * 36;
    int stb = BT ? 32 * (BN + 8) : BN * 36;
    return 3 * (sta + stb) * 4;
}

extern "C" void kernel_launch(void* const* d_in, const int* in_sizes, int n_in,
                              void* d_out, int out_size) {
    (void)in_sizes; (void)n_in; (void)out_size;

    const float* hidden  = (const float*)d_in[0];
    const float* enc     = (const float*)d_in[1];
    const float* wq  = (const float*)d_in[2];  const float* bq  = (const float*)d_in[3];
    const float* wk  = (const float*)d_in[4];  const float* bk  = (const float*)d_in[5];
    const float* wv  = (const float*)d_in[6];  const float* bv  = (const float*)d_in[7];
    const float* waq = (const float*)d_in[8];  const float* baq = (const float*)d_in[9];
    const float* wak = (const float*)d_in[10]; const float* bak = (const float*)d_in[11];
    const float* wav = (const float*)d_in[12]; const float* bav = (const float*)d_in[13];
    const float* nq  = (const float*)d_in[14]; const float* nk  = (const float*)d_in[15];
    const float* naq = (const float*)d_in[16]; const float* nak = (const float*)d_in[17];
    const float* w_out = (const float*)d_in[18]; const float* b_out = (const float*)d_in[19];
    const float* w_add = (const float*)d_in[20]; const float* b_add = (const float*)d_in[21];
    const float* img_cos = (const float*)d_in[22]; const float* img_sin = (const float*)d_in[23];
    const float* txt_cos = (const float*)d_in[24]; const float* txt_sin = (const float*)d_in[25];
    float* out = (float*)d_out;

    float *sQp, *sKp, *sVp, *Qhp, *Khp, *Vhp, *Pp, *Op;
    cudaGetSymbolAddress((void**)&sQp, g_sQ);
    cudaGetSymbolAddress((void**)&sKp, g_sK);
    cudaGetSymbolAddress((void**)&sVp, g_sV);
    cudaGetSymbolAddress((void**)&Qhp, g_Qh);
    cudaGetSymbolAddress((void**)&Khp, g_Kh);
    cudaGetSymbolAddress((void**)&Vhp, g_Vh);
    cudaGetSymbolAddress((void**)&Pp,  g_P);
    cudaGetSymbolAddress((void**)&Op,  g_O);

    const int SM_A = smem_bytes(128, 256, false);
    const int SM_B = smem_bytes(256, 128, true);
    cudaFuncSetAttribute(gemm_tf32<128, 256, false>,
                         cudaFuncAttributeMaxDynamicSharedMemorySize, SM_A);
    cudaFuncSetAttribute(gemm_tf32<256, 128, true>,
                         cudaFuncAttributeMaxDynamicSharedMemorySize, SM_B);

    // ---- 1) all 6 QKV projections in one launch ----
    {
        GemmP p = {};
        const float* As[6]   = {hidden, enc, hidden, enc, hidden, enc};
        const float* Bs[6]   = {wq, waq, wk, wak, wv, wav};
        float*       Cs[6]   = {sQp + (long long)S_TXTC * DMC, sQp,
                                sKp + (long long)S_TXTC * DMC, sKp,
                                sVp + (long long)S_TXTC * DMC, sVp};
        const float* bs[6]   = {bq, baq, bk, bak, bv, bav};
        int          ms[6]   = {S_IMGC / 128, S_TXTC / 128, S_IMGC / 128,
                                S_TXTC / 128, S_IMGC / 128, S_TXTC / 128};
        for (int j = 0; j < 6; j++) {
            p.Aa[j] = As[j]; p.Ba[j] = Bs[j]; p.Ca[j] = Cs[j];
            p.biasa[j] = bs[j]; p.my[j] = ms[j];
        }
        p.lda = DMC; p.ldb = DMC; p.ldc = DMC;
        p.alpha = 1.f; p.ktiles = DMC / 32;
        gemm_tf32<128, 256, false><<<dim3(DMC / 256, S_IMGC / 128, 6), 256, SM_A>>>(p);
    }

    // ---- 2) RMSNorm + RoPE + head-major layouts ----
    qkv_prep<<<dim3((S_TOTC * NHC) / 8, 3), 256>>>(
        sQp, sKp, sVp, nq, nk, naq, nak,
        img_cos, img_sin, txt_cos, txt_sin, Qhp, Khp, Vhp);

    // ---- 3) scores = scale * Q @ K^T, per head (24 jobs) ----
    {
        GemmP p = {};
        for (int j = 0; j < NHC; j++) {
            p.Aa[j] = Qhp + (long long)j * S_TOTC * HDC;
            p.Ba[j] = Khp + (long long)j * S_TOTC * HDC;
            p.Ca[j] = Pp  + (long long)j * S_TOTC * S_TOTC;
            p.biasa[j] = nullptr; p.my[j] = S_TOTC / 128;
        }
        p.lda = HDC; p.ldb = HDC; p.ldc = S_TOTC;
        p.alpha = 0.08838834764831845f; p.ktiles = HDC / 32;
        gemm_tf32<128, 256, false><<<dim3(S_TOTC / 256, S_TOTC / 128, NHC), 256, SM_A>>>(p);
    }

    // ---- 4) softmax over rows ----
    softmax_kernel<<<NHC * S_TOTC, 256>>>(Pp);

    // ---- 5) O = P @ V (transB path, head-major V), 24 jobs ----
    {
        GemmP p = {};
        for (int j = 0; j < NHC; j++) {
            p.Aa[j] = Pp  + (long long)j * S_TOTC * S_TOTC;
            p.Ba[j] = Vhp + (long long)j * S_TOTC * HDC;   // [s][d]
            p.Ca[j] = Op  + (long long)j * HDC;            // token-major, head offset
            p.biasa[j] = nullptr; p.my[j] = S_TOTC / 256;
        }
        p.lda = S_TOTC; p.ldb = HDC; p.ldc = DMC;
        p.alpha = 1.f; p.ktiles = S_TOTC / 32;
        gemm_tf32<256, 128, true><<<dim3(1, S_TOTC / 256, NHC), 256, SM_B>>>(p);
    }

    // ---- 6) output projections (2 jobs) ----
    {
        GemmP p = {};
        p.Aa[0] = Op + (long long)S_TXTC * DMC; p.Ba[0] = w_out;
        p.Ca[0] = out;                          p.biasa[0] = b_out;
        p.my[0] = S_IMGC / 128;
        p.Aa[1] = Op;                           p.Ba[1] = w_add;
        p.Ca[1] = out + (long long)S_IMGC * DMC; p.biasa[1] = b_add;
        p.my[1] = S_TXTC / 128;
        p.lda = DMC; p.ldb = DMC; p.ldc = DMC;
        p.alpha = 1.f; p.ktiles = DMC / 32;
        gemm_tf32<128, 256, false><<<dim3(DMC / 256, S_IMGC / 128, 2), 256, SM_A>>>(p);
    }
}

// round 11
// speedup vs baseline: 1.1833x; 1.0848x over previous
#include <cuda_runtime.h>
#include <cstdint>
#include <cstddef>

// Problem dims
#define S_IMGC 2304
#define S_TXTC 512
#define S_TOTC 2816
#define DMC    3072
#define NHC    24
#define HDC    128

// ---------------- scratch (static __device__, allocation-guard safe) ----------------
__device__ float g_sQ[S_TOTC * DMC];
__device__ float g_sK[S_TOTC * DMC];
__device__ float g_sV[S_TOTC * DMC];
__device__ float g_Qh[(size_t)NHC * S_TOTC * HDC];
__device__ float g_Kh[(size_t)NHC * S_TOTC * HDC];
__device__ float g_Vh[(size_t)NHC * S_TOTC * HDC];   // head-major [h][s][d]
__device__ float g_O [(size_t)S_TOTC * DMC];          // attn out, token-major

// ---------------- shared helpers ----------------
__device__ __forceinline__ void cpasync16(float* smem, const float* gmem) {
    uint32_t s = (uint32_t)__cvta_generic_to_shared(smem);
    asm volatile("cp.async.cg.shared.global [%0], [%1], 16;\n" :: "r"(s), "l"(gmem));
}

__device__ __forceinline__ uint32_t f2tf32(float x) {
    uint32_t r;
    asm("cvt.rna.tf32.f32 %0, %1;\n" : "=r"(r) : "f"(x));
    return r;
}

__device__ __forceinline__ void mma_tf32(float* c, const uint32_t* a, const uint32_t* b) {
    asm volatile(
        "mma.sync.aligned.m16n8k8.row.col.f32.tf32.tf32.f32 "
        "{%0,%1,%2,%3},{%4,%5,%6,%7},{%8,%9},{%0,%1,%2,%3};\n"
        : "+f"(c[0]), "+f"(c[1]), "+f"(c[2]), "+f"(c[3])
        : "r"(a[0]), "r"(a[1]), "r"(a[2]), "r"(a[3]), "r"(b[0]), "r"(b[1]));
}

// ---------------- multi-job tf32 GEMM (projections) ----------------
#define MAXJ 24
struct GemmP {
    const float* Aa[MAXJ];
    const float* Ba[MAXJ];
    float*       Ca[MAXJ];
    const float* biasa[MAXJ];
    int          my[MAXJ];
    long long lda, ldb, ldc;
    float alpha;
    int ktiles;
};

// Load a [ROWS x 32] K-major tile into smem rows of stride 36
template<int ROWS>
__device__ __forceinline__ void load_km(float* Ss, const float* G, long long ld,
                                        int tid, long long koff) {
    int rowl = tid >> 3;
    int chl  = (tid & 7) * 4;
#pragma unroll
    for (int r = rowl; r < ROWS; r += 32)
        cpasync16(Ss + r * 36 + chl, G + (long long)r * ld + koff + chl);
}

template<int BM, int BN>
__global__ __launch_bounds__(256, 1) void gemm_tf32(GemmP p) {
    constexpr int SROW  = 36;
    constexpr int STA   = BM * SROW;
    constexpr int STB   = BN * SROW;
    constexpr int NST   = 3;
    constexpr int WM    = BM / 64;

    extern __shared__ float smem[];
    float* sAb = smem;
    float* sBb = smem + NST * STA;

    int j = blockIdx.z;
    if ((int)blockIdx.y >= p.my[j]) return;

    int tid = threadIdx.x;
    const float* A = p.Aa[j] + (long long)blockIdx.y * BM * p.lda;
    const float* B = p.Ba[j] + (long long)blockIdx.x * BN * p.ldb;

    int wid = tid >> 5, lane = tid & 31;
    int wm = (wid % WM) * 64;
    int wn = (wid / WM) * 64;
    int g = lane >> 2, tg = lane & 3;

    float c[4][8][4];
#pragma unroll
    for (int mt = 0; mt < 4; mt++)
#pragma unroll
        for (int nt = 0; nt < 8; nt++)
#pragma unroll
            for (int r = 0; r < 4; r++) c[mt][nt][r] = 0.f;

    int npro = p.ktiles < 2 ? p.ktiles : 2;
    for (int s = 0; s < npro; s++) {
        load_km<BM>(sAb + s * STA, A, p.lda, tid, (long long)s * 32);
        load_km<BN>(sBb + s * STB, B, p.ldb, tid, (long long)s * 32);
        asm volatile("cp.async.commit_group;\n" ::: "memory");
    }

    for (int kt = 0; kt < p.ktiles; kt++) {
        if (kt < p.ktiles - 1) asm volatile("cp.async.wait_group 1;\n" ::: "memory");
        else                   asm volatile("cp.async.wait_group 0;\n" ::: "memory");
        __syncthreads();

        if (kt + 2 < p.ktiles) {
            int s = (kt + 2) % NST;
            load_km<BM>(sAb + s * STA, A, p.lda, tid, (long long)(kt + 2) * 32);
            load_km<BN>(sBb + s * STB, B, p.ldb, tid, (long long)(kt + 2) * 32);
            asm volatile("cp.async.commit_group;\n" ::: "memory");
        }

        const float* bA = sAb + (kt % NST) * STA;
        const float* bB = sBb + (kt % NST) * STB;

#pragma unroll
        for (int ks = 0; ks < 4; ks++) {
            int k0 = ks * 8 + tg;
            uint32_t af[4][4];
#pragma unroll
            for (int mt = 0; mt < 4; mt++) {
                const float* base = bA + (wm + mt * 16 + g) * SROW + k0;
                af[mt][0] = f2tf32(base[0]);
                af[mt][1] = f2tf32(base[8 * SROW]);
                af[mt][2] = f2tf32(base[4]);
                af[mt][3] = f2tf32(base[8 * SROW + 4]);
            }
            uint32_t bf[8][2];
#pragma unroll
            for (int nt = 0; nt < 8; nt++) {
                const float* base = bB + (wn + nt * 8 + g) * SROW + k0;
                bf[nt][0] = f2tf32(base[0]);
                bf[nt][1] = f2tf32(base[4]);
            }
#pragma unroll
            for (int mt = 0; mt < 4; mt++)
#pragma unroll
                for (int nt = 0; nt < 8; nt++)
                    mma_tf32(c[mt][nt], af[mt], bf[nt]);
        }
        __syncthreads();
    }

    float* C = p.Ca[j];
    const float* bias = p.biasa[j];
    long long r0 = (long long)blockIdx.y * BM + wm;
    long long c0 = (long long)blockIdx.x * BN + wn;
#pragma unroll
    for (int mt = 0; mt < 4; mt++) {
#pragma unroll
        for (int nt = 0; nt < 8; nt++) {
            long long col = c0 + nt * 8 + tg * 2;
            float b0 = 0.f, b1 = 0.f;
            if (bias) { b0 = bias[col]; b1 = bias[col + 1]; }
            long long r = r0 + mt * 16 + g;
            float2 v0 = make_float2(p.alpha * c[mt][nt][0] + b0, p.alpha * c[mt][nt][1] + b1);
            *(float2*)(C + r * p.ldc + col) = v0;
            float2 v1 = make_float2(p.alpha * c[mt][nt][2] + b0, p.alpha * c[mt][nt][3] + b1);
            *(float2*)(C + (r + 8) * p.ldc + col) = v1;
        }
    }
}

// ---------------- RMSNorm + RoPE + layout transform ----------------
// blockIdx.y: 0 -> Q (pre-scaled by 1/sqrt(HD)), 1 -> K, 2 -> V.
__global__ __launch_bounds__(256) void qkv_prep(
    const float* __restrict__ sQ, const float* __restrict__ sK, const float* __restrict__ sV,
    const float* __restrict__ nq, const float* __restrict__ nk,
    const float* __restrict__ naq, const float* __restrict__ nak,
    const float* __restrict__ img_cos, const float* __restrict__ img_sin,
    const float* __restrict__ txt_cos, const float* __restrict__ txt_sin,
    float* __restrict__ Qh, float* __restrict__ Kh, float* __restrict__ Vh)
{
    int unit = blockIdx.x * 8 + (threadIdx.x >> 5);
    int lane = threadIdx.x & 31;
    int which = blockIdx.y;
    if (unit >= S_TOTC * NHC) return;
    int tok = unit / NHC;
    int h = unit % NHC;

    const float* src = (which == 0) ? sQ : (which == 1) ? sK : sV;
    float4 x = *(const float4*)&src[(long long)tok * DMC + h * HDC + lane * 4];

    if (which < 2) {
        float ss = x.x * x.x + x.y * x.y + x.z * x.z + x.w * x.w;
#pragma unroll
        for (int o = 16; o > 0; o >>= 1) ss += __shfl_xor_sync(0xffffffffu, ss, o);
        float r = rsqrtf(ss * (1.0f / 128.0f) + 1e-6f);
        const float* nw = (which == 0) ? (tok < S_TXTC ? naq : nq)
                                       : (tok < S_TXTC ? nak : nk);
        float4 w = *(const float4*)&nw[lane * 4];
        x.x *= r * w.x; x.y *= r * w.y; x.z *= r * w.z; x.w *= r * w.w;

        const float* ct; const float* st; int tr;
        if (tok < S_TXTC) { ct = txt_cos; st = txt_sin; tr = tok; }
        else              { ct = img_cos; st = img_sin; tr = tok - S_TXTC; }
        int p0 = lane * 2;
        float c0 = ct[tr * 64 + p0],     s0 = st[tr * 64 + p0];
        float c1 = ct[tr * 64 + p0 + 1], s1 = st[tr * 64 + p0 + 1];
        float o0 = x.x * c0 - x.y * s0;
        float o1 = x.x * s0 + x.y * c0;
        float o2 = x.z * c1 - x.w * s1;
        float o3 = x.z * s1 + x.w * c1;
        x = make_float4(o0, o1, o2, o3);

        if (which == 0) {
            const float sc = 0.08838834764831845f;   // 1/sqrt(128) folded into Q
            x.x *= sc; x.y *= sc; x.z *= sc; x.w *= sc;
        }
        float* dst = (which == 0) ? Qh : Kh;
        *(float4*)&dst[((long long)h * S_TOTC + tok) * HDC + lane * 4] = x;
    } else {
        *(float4*)&Vh[((long long)h * S_TOTC + tok) * HDC + lane * 4] = x;
    }
}

// ---------------- fused flash attention ----------------
// grid (22 q-tiles, 24 heads), 256 threads (8 warps: 4 m-warps x 2 n-warps).
// smem (floats): Q[128][132] | K[2][64][132] | V[64][132] | P[128][68] | rM[128][2] | rS[128][2]
#define FA_SMEM_FLOATS (16896 + 16896 + 8448 + 8704 + 256 + 256)
#define FA_SMEM_BYTES  (FA_SMEM_FLOATS * 4)

__global__ __launch_bounds__(256, 1) void flash_attn(
    const float* __restrict__ Qh, const float* __restrict__ Kh,
    const float* __restrict__ Vh, float* __restrict__ Og)
{
    extern __shared__ float sm[];
    float* sQ = sm;                  // 128*132
    float* sK = sm + 16896;          // 2*64*132
    float* sV = sm + 33792;          // 64*132
    float* sP = sm + 42240;          // 128*68
    float* rM = sm + 50944;          // 128*2
    float* rS = sm + 51200;          // 128*2

    const int qt = blockIdx.x, h = blockIdx.y;
    const int tid = threadIdx.x;
    const int wid = tid >> 5, lane = tid & 31;
    const int g = lane >> 2, tg = lane & 3;
    const int wm  = (wid & 3) * 32;   // q rows of this warp
    const int nw  = wid >> 2;         // 0/1
    const int wns = nw * 32;          // S cols (kv) of this warp
    const int wno = nw * 64;          // O cols (d) of this warp

    const float* Qg = Qh + ((long long)h * S_TOTC + (long long)qt * 128) * HDC;
    const float* Kg = Kh + (long long)h * S_TOTC * HDC;
    const float* Vg = Vh + (long long)h * S_TOTC * HDC;

    // prologue: Q (16 passes) + K tile 0 (8 passes), one group
#pragma unroll
    for (int p_ = 0; p_ < 16; p_++) {
        int ch = tid + p_ * 256;
        int r = ch >> 5, c4 = (ch & 31) * 4;
        cpasync16(sQ + r * 132 + c4, Qg + (long long)r * HDC + c4);
    }
#pragma unroll
    for (int p_ = 0; p_ < 8; p_++) {
        int ch = tid + p_ * 256;
        int r = ch >> 5, c4 = (ch & 31) * 4;
        cpasync16(sK + r * 132 + c4, Kg + (long long)r * HDC + c4);
    }
    asm volatile("cp.async.commit_group;\n" ::: "memory");

    float o[2][8][4];
#pragma unroll
    for (int mt = 0; mt < 2; mt++)
#pragma unroll
        for (int nt = 0; nt < 8; nt++)
#pragma unroll
            for (int r = 0; r < 4; r++) o[mt][nt][r] = 0.f;
    float m[4] = {-1e30f, -1e30f, -1e30f, -1e30f};
    float l[4] = {0.f, 0.f, 0.f, 0.f};

    const int NIT = S_TOTC / 64;   // 44
    for (int it = 0; it < NIT; it++) {
        // prefetch next K tile
        if (it + 1 < NIT) {
            const float* Kn = Kg + (long long)(it + 1) * 64 * HDC;
            float* kd = sK + ((it + 1) & 1) * 8448;
#pragma unroll
            for (int p_ = 0; p_ < 8; p_++) {
                int ch = tid + p_ * 256;
                int r = ch >> 5, c4 = (ch & 31) * 4;
                cpasync16(kd + r * 132 + c4, Kn + (long long)r * HDC + c4);
            }
        }
        asm volatile("cp.async.commit_group;\n" ::: "memory");
        asm volatile("cp.async.wait_group 1;\n" ::: "memory");
        __syncthreads();   // K[it] visible to all; prev iter's PV reads of sV/sP done

        // V[it] load — overlaps S mma + softmax
        {
            const float* Vn = Vg + (long long)it * 64 * HDC;
#pragma unroll
            for (int p_ = 0; p_ < 8; p_++) {
                int ch = tid + p_ * 256;
                int r = ch >> 5, c4 = (ch & 31) * 4;
                cpasync16(sV + r * 132 + c4, Vn + (long long)r * HDC + c4);
            }
            asm volatile("cp.async.commit_group;\n" ::: "memory");
        }

        // ---- S = Q @ K^T (warp tile 32x32, fp32 accum) ----
        const float* bK = sK + (it & 1) * 8448;
        float c[2][4][4];
#pragma unroll
        for (int mt = 0; mt < 2; mt++)
#pragma unroll
            for (int nt = 0; nt < 4; nt++)
#pragma unroll
                for (int r = 0; r < 4; r++) c[mt][nt][r] = 0.f;

#pragma unroll
        for (int kc = 0; kc < 16; kc++) {
            int k0 = kc * 8 + tg;
            uint32_t af[2][4];
#pragma unroll
            for (int mt = 0; mt < 2; mt++) {
                const float* base = sQ + (wm + mt * 16 + g) * 132 + k0;
                af[mt][0] = f2tf32(base[0]);
                af[mt][1] = f2tf32(base[8 * 132]);
                af[mt][2] = f2tf32(base[4]);
                af[mt][3] = f2tf32(base[8 * 132 + 4]);
            }
            uint32_t bf[4][2];
#pragma unroll
            for (int nt = 0; nt < 4; nt++) {
                const float* base = bK + (wns + nt * 8 + g) * 132 + k0;
                bf[nt][0] = f2tf32(base[0]);
                bf[nt][1] = f2tf32(base[4]);
            }
#pragma unroll
            for (int mt = 0; mt < 2; mt++)
#pragma unroll
                for (int nt = 0; nt < 4; nt++)
                    mma_tf32(c[mt][nt], af[mt], bf[nt]);
        }

        // ---- softmax part 1: row max (quad shfl + cross-warp via smem) ----
        float lm[4];
#pragma unroll
        for (int mt = 0; mt < 2; mt++)
#pragma unroll
            for (int hh = 0; hh < 2; hh++) {
                float v = -1e30f;
#pragma unroll
                for (int nt = 0; nt < 4; nt++)
                    v = fmaxf(v, fmaxf(c[mt][nt][hh * 2], c[mt][nt][hh * 2 + 1]));
                lm[mt * 2 + hh] = v;
            }
#pragma unroll
        for (int r = 0; r < 4; r++) {
            lm[r] = fmaxf(lm[r], __shfl_xor_sync(0xffffffffu, lm[r], 1));
            lm[r] = fmaxf(lm[r], __shfl_xor_sync(0xffffffffu, lm[r], 2));
        }
        if (tg == 0) {
#pragma unroll
            for (int mt = 0; mt < 2; mt++)
#pragma unroll
                for (int hh = 0; hh < 2; hh++)
                    rM[(wm + mt * 16 + hh * 8 + g) * 2 + nw] = lm[mt * 2 + hh];
        }
        __syncthreads();

        // ---- part 2: combine max, exp, row sums ----
        float sc[4], ls[4];
#pragma unroll
        for (int mt = 0; mt < 2; mt++)
#pragma unroll
            for (int hh = 0; hh < 2; hh++) {
                int r = mt * 2 + hh;
                int row = wm + mt * 16 + hh * 8 + g;
                float mn = fmaxf(m[r], fmaxf(rM[row * 2], rM[row * 2 + 1]));
                sc[r] = __expf(m[r] - mn);
                m[r] = mn;
                ls[r] = 0.f;
            }
#pragma unroll
        for (int mt = 0; mt < 2; mt++)
#pragma unroll
            for (int nt = 0; nt < 4; nt++)
#pragma unroll
                for (int hh = 0; hh < 2; hh++) {
                    int r = mt * 2 + hh;
                    float p0 = __expf(c[mt][nt][hh * 2]     - m[r]);
                    float p1 = __expf(c[mt][nt][hh * 2 + 1] - m[r]);
                    c[mt][nt][hh * 2]     = p0;
                    c[mt][nt][hh * 2 + 1] = p1;
                    ls[r] += p0 + p1;
                }
#pragma unroll
        for (int r = 0; r < 4; r++) {
            ls[r] += __shfl_xor_sync(0xffffffffu, ls[r], 1);
            ls[r] += __shfl_xor_sync(0xffffffffu, ls[r], 2);
        }
        if (tg == 0) {
#pragma unroll
            for (int mt = 0; mt < 2; mt++)
#pragma unroll
                for (int hh = 0; hh < 2; hh++)
                    rS[(wm + mt * 16 + hh * 8 + g) * 2 + nw] = ls[mt * 2 + hh];
        }
        __syncthreads();

        // ---- part 3: l update, O rescale, stage P ----
#pragma unroll
        for (int mt = 0; mt < 2; mt++)
#pragma unroll
            for (int hh = 0; hh < 2; hh++) {
                int r = mt * 2 + hh;
                int row = wm + mt * 16 + hh * 8 + g;
                l[r] = l[r] * sc[r] + rS[row * 2] + rS[row * 2 + 1];
            }
#pragma unroll
        for (int mt = 0; mt < 2; mt++)
#pragma unroll
            for (int nt = 0; nt < 8; nt++) {
                o[mt][nt][0] *= sc[mt * 2];
                o[mt][nt][1] *= sc[mt * 2];
                o[mt][nt][2] *= sc[mt * 2 + 1];
                o[mt][nt][3] *= sc[mt * 2 + 1];
            }
#pragma unroll
        for (int mt = 0; mt < 2; mt++)
#pragma unroll
            for (int nt = 0; nt < 4; nt++) {
                int row = wm + mt * 16 + g;
                float* d = sP + row * 68 + wns + nt * 8 + tg * 2;
                d[0] = c[mt][nt][0];
                d[1] = c[mt][nt][1];
                d += 8 * 68;
                d[0] = c[mt][nt][2];
                d[1] = c[mt][nt][3];
            }
        asm volatile("cp.async.wait_group 0;\n" ::: "memory");
        __syncthreads();   // P staged + V[it] visible

        // ---- O += P @ V (warp tile 32x64) ----
#pragma unroll
        for (int kc = 0; kc < 8; kc++) {
            int k0 = kc * 8 + tg;
            uint32_t af[2][4];
#pragma unroll
            for (int mt = 0; mt < 2; mt++) {
                const float* base = sP + (wm + mt * 16 + g) * 68 + k0;
                af[mt][0] = f2tf32(base[0]);
                af[mt][1] = f2tf32(base[8 * 68]);
                af[mt][2] = f2tf32(base[4]);
                af[mt][3] = f2tf32(base[8 * 68 + 4]);
            }
            uint32_t bf[8][2];
#pragma unroll
            for (int nt = 0; nt < 8; nt++) {
                const float* base = sV + k0 * 132 + wno + nt * 8 + g;
                bf[nt][0] = f2tf32(base[0]);
                bf[nt][1] = f2tf32(base[4 * 132]);
            }
#pragma unroll
            for (int mt = 0; mt < 2; mt++)
#pragma unroll
                for (int nt = 0; nt < 8; nt++)
                    mma_tf32(o[mt][nt], af[mt], bf[nt]);
        }
    }

    // normalize + store token-major
    float invl[4];
#pragma unroll
    for (int r = 0; r < 4; r++) invl[r] = 1.f / l[r];
#pragma unroll
    for (int mt = 0; mt < 2; mt++)
#pragma unroll
        for (int nt = 0; nt < 8; nt++) {
            long long row = (long long)qt * 128 + wm + mt * 16 + g;
            long long col = (long long)h * HDC + wno + nt * 8 + tg * 2;
            float2 v0 = make_float2(o[mt][nt][0] * invl[mt * 2],
                                    o[mt][nt][1] * invl[mt * 2]);
            *(float2*)(Og + row * DMC + col) = v0;
            float2 v1 = make_float2(o[mt][nt][2] * invl[mt * 2 + 1],
                                    o[mt][nt][3] * invl[mt * 2 + 1]);
            *(float2*)(Og + (row + 8) * DMC + col) = v1;
        }
}

// ---------------- host orchestration ----------------
static constexpr int proj_smem_bytes() {
    return 3 * (128 * 36 + 256 * 36) * 4;
}

extern "C" void kernel_launch(void* const* d_in, const int* in_sizes, int n_in,
                              void* d_out, int out_size) {
    (void)in_sizes; (void)n_in; (void)out_size;

    const float* hidden  = (const float*)d_in[0];
    const float* enc     = (const float*)d_in[1];
    const float* wq  = (const float*)d_in[2];  const float* bq  = (const float*)d_in[3];
    const float* wk  = (const float*)d_in[4];  const float* bk  = (const float*)d_in[5];
    const float* wv  = (const float*)d_in[6];  const float* bv  = (const float*)d_in[7];
    const float* waq = (const float*)d_in[8];  const float* baq = (const float*)d_in[9];
    const float* wak = (const float*)d_in[10]; const float* bak = (const float*)d_in[11];
    const float* wav = (const float*)d_in[12]; const float* bav = (const float*)d_in[13];
    const float* nq  = (const float*)d_in[14]; const float* nk  = (const float*)d_in[15];
    const float* naq = (const float*)d_in[16]; const float* nak = (const float*)d_in[17];
    const float* w_out = (const float*)d_in[18]; const float* b_out = (const float*)d_in[19];
    const float* w_add = (const float*)d_in[20]; const float* b_add = (const float*)d_in[21];
    const float* img_cos = (const float*)d_in[22]; const float* img_sin = (const float*)d_in[23];
    const float* txt_cos = (const float*)d_in[24]; const float* txt_sin = (const float*)d_in[25];
    float* out = (float*)d_out;

    float *sQp, *sKp, *sVp, *Qhp, *Khp, *Vhp, *Op;
    cudaGetSymbolAddress((void**)&sQp, g_sQ);
    cudaGetSymbolAddress((void**)&sKp, g_sK);
    cudaGetSymbolAddress((void**)&sVp, g_sV);
    cudaGetSymbolAddress((void**)&Qhp, g_Qh);
    cudaGetSymbolAddress((void**)&Khp, g_Kh);
    cudaGetSymbolAddress((void**)&Vhp, g_Vh);
    cudaGetSymbolAddress((void**)&Op,  g_O);

    const int SM_A = proj_smem_bytes();
    cudaFuncSetAttribute(gemm_tf32<128, 256>,
                         cudaFuncAttributeMaxDynamicSharedMemorySize, SM_A);
    cudaFuncSetAttribute(flash_attn,
                         cudaFuncAttributeMaxDynamicSharedMemorySize, FA_SMEM_BYTES);

    // ---- 1) all 6 QKV projections in one launch ----
    {
        GemmP p = {};
        const float* As[6]   = {hidden, enc, hidden, enc, hidden, enc};
        const float* Bs[6]   = {wq, waq, wk, wak, wv, wav};
        float*       Cs[6]   = {sQp + (long long)S_TXTC * DMC, sQp,
                                sKp + (long long)S_TXTC * DMC, sKp,
                                sVp + (long long)S_TXTC * DMC, sVp};
        const float* bs[6]   = {bq, baq, bk, bak, bv, bav};
        int          ms[6]   = {S_IMGC / 128, S_TXTC / 128, S_IMGC / 128,
                                S_TXTC / 128, S_IMGC / 128, S_TXTC / 128};
        for (int j = 0; j < 6; j++) {
            p.Aa[j] = As[j]; p.Ba[j] = Bs[j]; p.Ca[j] = Cs[j];
            p.biasa[j] = bs[j]; p.my[j] = ms[j];
        }
        p.lda = DMC; p.ldb = DMC; p.ldc = DMC;
        p.alpha = 1.f; p.ktiles = DMC / 32;
        gemm_tf32<128, 256><<<dim3(DMC / 256, S_IMGC / 128, 6), 256, SM_A>>>(p);
    }

    // ---- 2) RMSNorm + RoPE + head-major layouts (Q pre-scaled) ----
    qkv_prep<<<dim3((S_TOTC * NHC) / 8, 3), 256>>>(
        sQp, sKp, sVp, nq, nk, naq, nak,
        img_cos, img_sin, txt_cos, txt_sin, Qhp, Khp, Vhp);

    // ---- 3) fused flash attention -> g_O token-major ----
    flash_attn<<<dim3(S_TOTC / 128, NHC), 256, FA_SMEM_BYTES>>>(Qhp, Khp, Vhp, Op);

    // ---- 4) output projections (2 jobs) ----
    {
        GemmP p = {};
        p.Aa[0] = Op + (long long)S_TXTC * DMC; p.Ba[0] = w_out;
        p.Ca[0] = out;                           p.biasa[0] = b_out;
        p.my[0] = S_IMGC / 128;
        p.Aa[1] = Op;                            p.Ba[1] = w_add;
        p.Ca[1] = out + (long long)S_IMGC * DMC; p.biasa[1] = b_add;
        p.my[1] = S_TXTC / 128;
        p.lda = DMC; p.ldb = DMC; p.ldc = DMC;
        p.alpha = 1.f; p.ktiles = DMC / 32;
        gemm_tf32<128, 256><<<dim3(DMC / 256, S_IMGC / 128, 2), 256, SM_A>>>(p);
    }
}